// round 5
// baseline (speedup 1.0000x reference)
#include <cuda_runtime.h>
#include <cstdint>

#define DEVINL __device__ __forceinline__

// ---------------- problem dims ----------------
#define B_SZ   8
#define S_SZ   4096
#define D_IN   1280
#define D_OUT  1280
#define N_L    4
#define R_L    16
#define J_L    64                 /* N_L * R_L */
#define M_ROWS 32768              /* B_SZ * S_SZ */
#define K_TOT  1344               /* D_IN + J_L  */

// ---------------- tiling ----------------
#define KC    16                  /* K per smem stage */
#define SA    136                 /* smem stride (floats) for 128-wide tiles: 136%32==8 -> conflict-free */
#define SB1   72                  /* smem stride for 64-wide tile: 72%32==8 */
#define NT_MAIN (K_TOT / KC)      /* 84 */
#define NT_G    (D_IN / KC)       /* 80 */

// LoRA intermediate: g[m][j] = scaling[j>>4] * mask[j>>4][m & 4095] * (x[m] . Acat[j])
__device__ float g_scratch[(size_t)M_ROWS * J_L];

// ---------------- helpers ----------------
DEVINL uint32_t tf32b(float x) {          // round-to-nearest tf32 (unbiased) kept in b32
    uint32_t r;
    asm("cvt.rna.tf32.f32 %0, %1;" : "=r"(r) : "f"(x));
    return r;
}

DEVINL void mma_tf32(float c[4], uint32_t a0, uint32_t a1, uint32_t a2, uint32_t a3,
                     uint32_t b0, uint32_t b1) {
    asm volatile(
        "mma.sync.aligned.m16n8k8.row.col.f32.tf32.tf32.f32 "
        "{%0,%1,%2,%3}, {%4,%5,%6,%7}, {%8,%9}, {%0,%1,%2,%3};"
        : "+f"(c[0]), "+f"(c[1]), "+f"(c[2]), "+f"(c[3])
        : "r"(a0), "r"(a1), "r"(a2), "r"(a3), "r"(b0), "r"(b1));
}

// ============================================================================
// Kernel 1: g = (scaling * mask) .* (X @ Acat^T)    [32768 x 64, K = 1280]
//   256 threads, 128x64 CTA tile, 8 warps as 4(m) x 2(n), warp tile 32x32.
// ============================================================================
__global__ void __launch_bounds__(256, 2)
lora_g_kernel(const float* __restrict__ X, const float* __restrict__ Acat,
              const float* __restrict__ scalings, const float* __restrict__ masks)
{
    __shared__ uint32_t As[2][KC * SA];   // [k][m], m-contig
    __shared__ uint32_t Bs[2][KC * SB1];  // [k][n]

    const int tid  = threadIdx.x;
    const int mb   = blockIdx.x * 128;
    const int lane = tid & 31;
    const int wid  = tid >> 5;
    const int gid  = lane >> 2, tig = lane & 3;
    const int moff = (wid >> 1) * 32;
    const int noff = (wid & 1) * 32;

    // fill mappings
    const int rA  = tid & 127;            // A row, 2 float4 per thread
    const int cgA = (tid >> 7) * 2;       // k-groups cgA, cgA+1
    const int rB  = tid & 63;             // B row, 1 float4 per thread
    const int cgB = (tid >> 6) & 3;

    float acc[2][4][4];
    #pragma unroll
    for (int mi = 0; mi < 2; mi++)
        #pragma unroll
        for (int ni = 0; ni < 4; ni++)
            #pragma unroll
            for (int q = 0; q < 4; q++) acc[mi][ni][q] = 0.f;

    float4 ra0, ra1, rb;
    auto ldg = [&](int t) {
        int kb = t * KC;
        const float* pa = X + (size_t)(mb + rA) * D_IN + kb + cgA * 4;
        ra0 = ((const float4*)pa)[0];
        ra1 = ((const float4*)pa)[1];
        rb  = *(const float4*)(Acat + (size_t)rB * D_IN + kb + cgB * 4);
    };
    auto sts = [&](int buf) {
        uint32_t* a = As[buf] + rA;
        a[(cgA * 4 + 0) * SA] = tf32b(ra0.x);
        a[(cgA * 4 + 1) * SA] = tf32b(ra0.y);
        a[(cgA * 4 + 2) * SA] = tf32b(ra0.z);
        a[(cgA * 4 + 3) * SA] = tf32b(ra0.w);
        a[(cgA * 4 + 4) * SA] = tf32b(ra1.x);
        a[(cgA * 4 + 5) * SA] = tf32b(ra1.y);
        a[(cgA * 4 + 6) * SA] = tf32b(ra1.z);
        a[(cgA * 4 + 7) * SA] = tf32b(ra1.w);
        uint32_t* b = Bs[buf] + rB;
        b[(cgB * 4 + 0) * SB1] = tf32b(rb.x);
        b[(cgB * 4 + 1) * SB1] = tf32b(rb.y);
        b[(cgB * 4 + 2) * SB1] = tf32b(rb.z);
        b[(cgB * 4 + 3) * SB1] = tf32b(rb.w);
    };
    auto domma = [&](int buf) {
        #pragma unroll
        for (int ks = 0; ks < 2; ks++) {
            const int k0 = ks * 8;
            uint32_t af[2][4], bf[4][2];
            #pragma unroll
            for (int mi = 0; mi < 2; mi++) {
                const uint32_t* p = As[buf] + moff + mi * 16 + gid;
                af[mi][0] = p[(k0 + tig) * SA];
                af[mi][1] = p[(k0 + tig) * SA + 8];
                af[mi][2] = p[(k0 + tig + 4) * SA];
                af[mi][3] = p[(k0 + tig + 4) * SA + 8];
            }
            #pragma unroll
            for (int ni = 0; ni < 4; ni++) {
                const uint32_t* p = Bs[buf] + noff + ni * 8 + gid;
                bf[ni][0] = p[(k0 + tig) * SB1];
                bf[ni][1] = p[(k0 + tig + 4) * SB1];
            }
            #pragma unroll
            for (int mi = 0; mi < 2; mi++)
                #pragma unroll
                for (int ni = 0; ni < 4; ni++)
                    mma_tf32(acc[mi][ni], af[mi][0], af[mi][1], af[mi][2], af[mi][3],
                             bf[ni][0], bf[ni][1]);
        }
    };

    ldg(0); sts(0); ldg(1);
    __syncthreads();
    for (int t = 0; t < NT_G; t++) {
        if (t + 1 < NT_G) {
            sts((t + 1) & 1);
            if (t + 2 < NT_G) ldg(t + 2);
        }
        domma(t & 1);
        __syncthreads();
    }

    // epilogue: coef = scaling * mask, per (mi, row-half, subject-local)
    float coef[2][2][2];
    #pragma unroll
    for (int mi = 0; mi < 2; mi++)
        #pragma unroll
        for (int h = 0; h < 2; h++) {
            int m = mb + moff + mi * 16 + gid + h * 8;
            int s = m & (S_SZ - 1);
            #pragma unroll
            for (int sl = 0; sl < 2; sl++) {
                int subj = (noff >> 4) + sl;
                coef[mi][h][sl] = scalings[subj] * masks[subj * S_SZ + s];
            }
        }
    #pragma unroll
    for (int mi = 0; mi < 2; mi++)
        #pragma unroll
        for (int ni = 0; ni < 4; ni++) {
            int col = noff + ni * 8 + 2 * tig;
            int sl  = (ni * 8 + 2 * tig) >> 4;
            int row0 = mb + moff + mi * 16 + gid;
            float2 v0 = { acc[mi][ni][0] * coef[mi][0][sl], acc[mi][ni][1] * coef[mi][0][sl] };
            float2 v1 = { acc[mi][ni][2] * coef[mi][1][sl], acc[mi][ni][3] * coef[mi][1][sl] };
            *(float2*)(g_scratch + (size_t)row0 * J_L + col)       = v0;
            *(float2*)(g_scratch + (size_t)(row0 + 8) * J_L + col) = v1;
        }
}

// ============================================================================
// Kernel 2: out = X @ W^T + bias + g @ Bcat^T   [one GEMM, K = 1344]
//   512 threads, 128x128 CTA tile, 16 warps as 4(m) x 4(n), warp tile 32x32.
// ============================================================================
__global__ void __launch_bounds__(512, 1)
lora_main_kernel(const float* __restrict__ X, const float* __restrict__ W,
                 const float* __restrict__ bias, const float* __restrict__ Bw,
                 float* __restrict__ out)
{
    __shared__ uint32_t As[2][KC * SA];
    __shared__ uint32_t Bs[2][KC * SA];

    const int tid  = threadIdx.x;
    const int nb   = blockIdx.x * 128;   // x fastest: 10 CTAs share one X tile via L2
    const int mb   = blockIdx.y * 128;
    const int lane = tid & 31;
    const int wid  = tid >> 5;
    const int gid  = lane >> 2, tig = lane & 3;
    const int moff = (wid >> 2) * 32;
    const int noff = (wid & 3) * 32;

    const int r  = tid & 127;            // fill row (A and B), 1 float4 each
    const int cg = tid >> 7;             // 0..3

    float acc[2][4][4];
    #pragma unroll
    for (int mi = 0; mi < 2; mi++)
        #pragma unroll
        for (int ni = 0; ni < 4; ni++)
            #pragma unroll
            for (int q = 0; q < 4; q++) acc[mi][ni][q] = 0.f;

    float4 ra, rb;
    auto ldg = [&](int t) {
        int kb = t * KC;
        if (kb < D_IN) {
            ra = *(const float4*)(X + (size_t)(mb + r) * D_IN + kb + cg * 4);
            rb = *(const float4*)(W + (size_t)(nb + r) * D_IN + kb + cg * 4);
        } else {
            int j0 = (kb - D_IN) + cg * 4;
            ra = *(const float4*)(g_scratch + (size_t)(mb + r) * J_L + j0);
            // Bcat[o][j] = Bw[j>>4][o][j&15]
            rb = *(const float4*)(Bw + (size_t)(j0 >> 4) * (D_OUT * R_L)
                                     + (size_t)(nb + r) * R_L + (j0 & 15));
        }
    };
    auto sts = [&](int buf) {
        uint32_t* a = As[buf] + r;
        a[(cg * 4 + 0) * SA] = tf32b(ra.x);
        a[(cg * 4 + 1) * SA] = tf32b(ra.y);
        a[(cg * 4 + 2) * SA] = tf32b(ra.z);
        a[(cg * 4 + 3) * SA] = tf32b(ra.w);
        uint32_t* b = Bs[buf] + r;
        b[(cg * 4 + 0) * SA] = tf32b(rb.x);
        b[(cg * 4 + 1) * SA] = tf32b(rb.y);
        b[(cg * 4 + 2) * SA] = tf32b(rb.z);
        b[(cg * 4 + 3) * SA] = tf32b(rb.w);
    };
    auto domma = [&](int buf) {
        #pragma unroll
        for (int ks = 0; ks < 2; ks++) {
            const int k0 = ks * 8;
            uint32_t af[2][4], bf[4][2];
            #pragma unroll
            for (int mi = 0; mi < 2; mi++) {
                const uint32_t* p = As[buf] + moff + mi * 16 + gid;
                af[mi][0] = p[(k0 + tig) * SA];
                af[mi][1] = p[(k0 + tig) * SA + 8];
                af[mi][2] = p[(k0 + tig + 4) * SA];
                af[mi][3] = p[(k0 + tig + 4) * SA + 8];
            }
            #pragma unroll
            for (int ni = 0; ni < 4; ni++) {
                const uint32_t* p = Bs[buf] + noff + ni * 8 + gid;
                bf[ni][0] = p[(k0 + tig) * SA];
                bf[ni][1] = p[(k0 + tig + 4) * SA];
            }
            #pragma unroll
            for (int mi = 0; mi < 2; mi++)
                #pragma unroll
                for (int ni = 0; ni < 4; ni++)
                    mma_tf32(acc[mi][ni], af[mi][0], af[mi][1], af[mi][2], af[mi][3],
                             bf[ni][0], bf[ni][1]);
        }
    };

    ldg(0); sts(0); ldg(1);
    __syncthreads();
    for (int t = 0; t < NT_MAIN; t++) {
        if (t + 1 < NT_MAIN) {
            sts((t + 1) & 1);
            if (t + 2 < NT_MAIN) ldg(t + 2);
        }
        domma(t & 1);
        __syncthreads();
    }

    // epilogue: + bias, float2 stores (4 lanes cover a 32B sector)
    #pragma unroll
    for (int ni = 0; ni < 4; ni++) {
        int col = nb + noff + ni * 8 + 2 * tig;
        float2 bb = *(const float2*)(bias + col);
        #pragma unroll
        for (int mi = 0; mi < 2; mi++) {
            int row0 = mb + moff + mi * 16 + gid;
            float2 v0 = { acc[mi][ni][0] + bb.x, acc[mi][ni][1] + bb.y };
            float2 v1 = { acc[mi][ni][2] + bb.x, acc[mi][ni][3] + bb.y };
            *(float2*)(out + (size_t)row0 * D_OUT + col)       = v0;
            *(float2*)(out + (size_t)(row0 + 8) * D_OUT + col) = v1;
        }
    }
}

// ============================================================================
extern "C" void kernel_launch(void* const* d_in, const int* in_sizes, int n_in,
                              void* d_out, int out_size)
{
    (void)in_sizes; (void)n_in; (void)out_size;
    const float* X     = (const float*)d_in[0];
    const float* W     = (const float*)d_in[1];
    const float* bias  = (const float*)d_in[2];
    const float* Acat  = (const float*)d_in[3];   // (N,R,D) flattens to (64,1280)
    const float* Bw    = (const float*)d_in[4];
    const float* scal  = (const float*)d_in[5];
    const float* masks = (const float*)d_in[6];
    float* out = (float*)d_out;

    lora_g_kernel<<<M_ROWS / 128, 256>>>(X, Acat, scal, masks);
    lora_main_kernel<<<dim3(D_OUT / 128, M_ROWS / 128), 512>>>(X, W, bias, Bw, out);
}

// round 6
// speedup vs baseline: 1.3646x; 1.3646x over previous
#include <cuda_runtime.h>
#include <cstdint>

#define DEVINL __device__ __forceinline__

// ---------------- problem dims ----------------
#define B_SZ   8
#define S_SZ   4096
#define D_IN   1280
#define D_OUT  1280
#define N_L    4
#define R_L    16
#define J_L    64                 /* N_L * R_L */
#define M_ROWS 32768              /* B_SZ * S_SZ */
#define K_TOT  1344               /* D_IN + J_L  */

// ---------------- tiling ----------------
#define KC    16                  /* K per smem stage */
#define SA    136                 /* smem stride (floats): 136%32==8 -> conflict-free */
#define SB1   72                  /* stride for 64-wide tile (g kernel) */
#define NT_MAIN (K_TOT / KC)      /* 84 */
#define NT_G    (D_IN / KC)       /* 80 */

// LoRA intermediate: g[m][j] = scaling[j>>4] * mask[j>>4][m & 4095] * (x[m] . Acat[j])
__device__ float g_scratch[(size_t)M_ROWS * J_L];

// ---------------- helpers ----------------
DEVINL uint32_t tf32b(float x) {          // round-to-nearest tf32 (unbiased) kept in b32
    uint32_t r;
    asm("cvt.rna.tf32.f32 %0, %1;" : "=r"(r) : "f"(x));
    return r;
}

DEVINL void mma_tf32(float c[4], uint32_t a0, uint32_t a1, uint32_t a2, uint32_t a3,
                     uint32_t b0, uint32_t b1) {
    asm volatile(
        "mma.sync.aligned.m16n8k8.row.col.f32.tf32.tf32.f32 "
        "{%0,%1,%2,%3}, {%4,%5,%6,%7}, {%8,%9}, {%0,%1,%2,%3};"
        : "+f"(c[0]), "+f"(c[1]), "+f"(c[2]), "+f"(c[3])
        : "r"(a0), "r"(a1), "r"(a2), "r"(a3), "r"(b0), "r"(b1));
}

// ============================================================================
// Kernel 1: g = (scaling * mask) .* (X @ Acat^T)    [32768 x 64, K = 1280]
//   256 threads, 128x64 CTA tile, 8 warps as 4(m) x 2(n), warp tile 32x32.
// ============================================================================
__global__ void __launch_bounds__(256, 2)
lora_g_kernel(const float* __restrict__ X, const float* __restrict__ Acat,
              const float* __restrict__ scalings, const float* __restrict__ masks)
{
    __shared__ uint32_t As[2][KC * SA];   // [k][m], m-contig
    __shared__ uint32_t Bs[2][KC * SB1];  // [k][n]

    const int tid  = threadIdx.x;
    const int mb   = blockIdx.x * 128;
    const int lane = tid & 31;
    const int wid  = tid >> 5;
    const int gid  = lane >> 2, tig = lane & 3;
    const int moff = (wid >> 1) * 32;
    const int noff = (wid & 1) * 32;

    // fill mappings
    const int rA  = tid & 127;            // A row, 2 float4 per thread
    const int cgA = (tid >> 7) * 2;       // k-groups cgA, cgA+1
    const int rB  = tid & 63;             // B row, 1 float4 per thread
    const int cgB = (tid >> 6) & 3;

    float acc[2][4][4];
    #pragma unroll
    for (int mi = 0; mi < 2; mi++)
        #pragma unroll
        for (int ni = 0; ni < 4; ni++)
            #pragma unroll
            for (int q = 0; q < 4; q++) acc[mi][ni][q] = 0.f;

    float4 ra0, ra1, rb;
    auto ldg = [&](int t) {
        int kb = t * KC;
        const float* pa = X + (size_t)(mb + rA) * D_IN + kb + cgA * 4;
        ra0 = ((const float4*)pa)[0];
        ra1 = ((const float4*)pa)[1];
        rb  = *(const float4*)(Acat + (size_t)rB * D_IN + kb + cgB * 4);
    };
    auto sts = [&](int buf) {
        uint32_t* a = As[buf] + rA;
        a[(cgA * 4 + 0) * SA] = tf32b(ra0.x);
        a[(cgA * 4 + 1) * SA] = tf32b(ra0.y);
        a[(cgA * 4 + 2) * SA] = tf32b(ra0.z);
        a[(cgA * 4 + 3) * SA] = tf32b(ra0.w);
        a[(cgA * 4 + 4) * SA] = tf32b(ra1.x);
        a[(cgA * 4 + 5) * SA] = tf32b(ra1.y);
        a[(cgA * 4 + 6) * SA] = tf32b(ra1.z);
        a[(cgA * 4 + 7) * SA] = tf32b(ra1.w);
        uint32_t* b = Bs[buf] + rB;
        b[(cgB * 4 + 0) * SB1] = tf32b(rb.x);
        b[(cgB * 4 + 1) * SB1] = tf32b(rb.y);
        b[(cgB * 4 + 2) * SB1] = tf32b(rb.z);
        b[(cgB * 4 + 3) * SB1] = tf32b(rb.w);
    };
    auto domma = [&](int buf) {
        #pragma unroll
        for (int ks = 0; ks < 2; ks++) {
            const int k0 = ks * 8;
            uint32_t af[2][4], bf[4][2];
            #pragma unroll
            for (int mi = 0; mi < 2; mi++) {
                const uint32_t* p = As[buf] + moff + mi * 16 + gid;
                af[mi][0] = p[(k0 + tig) * SA];
                af[mi][1] = p[(k0 + tig) * SA + 8];
                af[mi][2] = p[(k0 + tig + 4) * SA];
                af[mi][3] = p[(k0 + tig + 4) * SA + 8];
            }
            #pragma unroll
            for (int ni = 0; ni < 4; ni++) {
                const uint32_t* p = Bs[buf] + noff + ni * 8 + gid;
                bf[ni][0] = p[(k0 + tig) * SB1];
                bf[ni][1] = p[(k0 + tig + 4) * SB1];
            }
            #pragma unroll
            for (int mi = 0; mi < 2; mi++)
                #pragma unroll
                for (int ni = 0; ni < 4; ni++)
                    mma_tf32(acc[mi][ni], af[mi][0], af[mi][1], af[mi][2], af[mi][3],
                             bf[ni][0], bf[ni][1]);
        }
    };

    ldg(0); sts(0); ldg(1);
    __syncthreads();
    for (int t = 0; t < NT_G; t++) {
        if (t + 1 < NT_G) {
            sts((t + 1) & 1);
            if (t + 2 < NT_G) ldg(t + 2);
        }
        domma(t & 1);
        __syncthreads();
    }

    // epilogue: coef = scaling * mask, per (mi, row-half, subject-local)
    float coef[2][2][2];
    #pragma unroll
    for (int mi = 0; mi < 2; mi++)
        #pragma unroll
        for (int h = 0; h < 2; h++) {
            int m = mb + moff + mi * 16 + gid + h * 8;
            int s = m & (S_SZ - 1);
            #pragma unroll
            for (int sl = 0; sl < 2; sl++) {
                int subj = (noff >> 4) + sl;
                coef[mi][h][sl] = scalings[subj] * masks[subj * S_SZ + s];
            }
        }
    #pragma unroll
    for (int mi = 0; mi < 2; mi++)
        #pragma unroll
        for (int ni = 0; ni < 4; ni++) {
            int col = noff + ni * 8 + 2 * tig;
            int sl  = (ni * 8 + 2 * tig) >> 4;
            int row0 = mb + moff + mi * 16 + gid;
            float2 v0 = { acc[mi][ni][0] * coef[mi][0][sl], acc[mi][ni][1] * coef[mi][0][sl] };
            float2 v1 = { acc[mi][ni][2] * coef[mi][1][sl], acc[mi][ni][3] * coef[mi][1][sl] };
            *(float2*)(g_scratch + (size_t)row0 * J_L + col)       = v0;
            *(float2*)(g_scratch + (size_t)(row0 + 8) * J_L + col) = v1;
        }
}

// ============================================================================
// Kernel 2: out = X @ W^T + bias + g @ Bcat^T   [one GEMM, K = 1344]
//   128 threads, 128x128 CTA tile, 4 warps as 2(m) x 2(n), warp tile 64x64.
//   2 CTAs/SM: one CTA's MMA phase covers the other's fill/sync bubbles.
// ============================================================================
__global__ void __launch_bounds__(128, 2)
lora_main_kernel(const float* __restrict__ X, const float* __restrict__ W,
                 const float* __restrict__ bias, const float* __restrict__ Bw,
                 float* __restrict__ out)
{
    __shared__ uint32_t As[2][KC * SA];   // [k][m]
    __shared__ uint32_t Bs[2][KC * SA];   // [k][n]

    const int tid  = threadIdx.x;
    const int nb   = blockIdx.x * 128;    // x fastest: 10 CTAs share the X tile via L2
    const int mb   = blockIdx.y * 128;
    const int lane = tid & 31;
    const int wid  = tid >> 5;
    const int gid  = lane >> 2, tig = lane & 3;
    const int moff = (wid & 1) * 64;
    const int noff = (wid >> 1) * 64;

    float acc[4][8][4];                   // 64x64 warp tile -> 128 floats
    #pragma unroll
    for (int mi = 0; mi < 4; mi++)
        #pragma unroll
        for (int ni = 0; ni < 8; ni++)
            #pragma unroll
            for (int q = 0; q < 4; q++) acc[mi][ni][q] = 0.f;

    // fill: one row per thread, 4 contiguous float4 (64B) per tile per stage
    float4 ra[4], rb[4];
    auto ldg = [&](int t) {
        int kb = t * KC;
        if (kb < D_IN) {
            const float4* pa = (const float4*)(X + (size_t)(mb + tid) * D_IN + kb);
            const float4* pb = (const float4*)(W + (size_t)(nb + tid) * D_IN + kb);
            #pragma unroll
            for (int kg = 0; kg < 4; kg++) { ra[kg] = pa[kg]; rb[kg] = pb[kg]; }
        } else {
            int j0 = kb - D_IN;
            const float4* pa = (const float4*)(g_scratch + (size_t)(mb + tid) * J_L + j0);
            // Bcat[o][j] = Bw[j>>4][o][j&15]; j0 is a multiple of 16 -> one Bw row slab
            const float4* pb = (const float4*)(Bw + (size_t)(j0 >> 4) * (D_OUT * R_L)
                                                  + (size_t)(nb + tid) * R_L);
            #pragma unroll
            for (int kg = 0; kg < 4; kg++) { ra[kg] = pa[kg]; rb[kg] = pb[kg]; }
        }
    };
    auto sts = [&](int buf) {
        uint32_t* a = As[buf] + tid;
        uint32_t* b = Bs[buf] + tid;
        #pragma unroll
        for (int kg = 0; kg < 4; kg++) {
            a[(kg * 4 + 0) * SA] = tf32b(ra[kg].x);
            a[(kg * 4 + 1) * SA] = tf32b(ra[kg].y);
            a[(kg * 4 + 2) * SA] = tf32b(ra[kg].z);
            a[(kg * 4 + 3) * SA] = tf32b(ra[kg].w);
            b[(kg * 4 + 0) * SA] = tf32b(rb[kg].x);
            b[(kg * 4 + 1) * SA] = tf32b(rb[kg].y);
            b[(kg * 4 + 2) * SA] = tf32b(rb[kg].z);
            b[(kg * 4 + 3) * SA] = tf32b(rb[kg].w);
        }
    };
    auto domma = [&](int buf) {
        #pragma unroll
        for (int ks = 0; ks < 2; ks++) {
            const int k0 = ks * 8;
            uint32_t af[4][4], bf[8][2];
            #pragma unroll
            for (int mi = 0; mi < 4; mi++) {
                const uint32_t* p = As[buf] + moff + mi * 16 + gid;
                af[mi][0] = p[(k0 + tig) * SA];
                af[mi][1] = p[(k0 + tig) * SA + 8];
                af[mi][2] = p[(k0 + tig + 4) * SA];
                af[mi][3] = p[(k0 + tig + 4) * SA + 8];
            }
            #pragma unroll
            for (int ni = 0; ni < 8; ni++) {
                const uint32_t* p = Bs[buf] + noff + ni * 8 + gid;
                bf[ni][0] = p[(k0 + tig) * SA];
                bf[ni][1] = p[(k0 + tig + 4) * SA];
            }
            #pragma unroll
            for (int mi = 0; mi < 4; mi++)
                #pragma unroll
                for (int ni = 0; ni < 8; ni++)
                    mma_tf32(acc[mi][ni], af[mi][0], af[mi][1], af[mi][2], af[mi][3],
                             bf[ni][0], bf[ni][1]);
        }
    };

    ldg(0); sts(0); ldg(1);
    __syncthreads();
    for (int t = 0; t < NT_MAIN; t++) {
        if (t + 1 < NT_MAIN) {
            sts((t + 1) & 1);
            if (t + 2 < NT_MAIN) ldg(t + 2);
        }
        domma(t & 1);
        __syncthreads();
    }

    // epilogue: + bias, float2 stores
    #pragma unroll
    for (int ni = 0; ni < 8; ni++) {
        int col = nb + noff + ni * 8 + 2 * tig;
        float2 bb = *(const float2*)(bias + col);
        #pragma unroll
        for (int mi = 0; mi < 4; mi++) {
            int row0 = mb + moff + mi * 16 + gid;
            float2 v0 = { acc[mi][ni][0] + bb.x, acc[mi][ni][1] + bb.y };
            float2 v1 = { acc[mi][ni][2] + bb.x, acc[mi][ni][3] + bb.y };
            *(float2*)(out + (size_t)row0 * D_OUT + col)       = v0;
            *(float2*)(out + (size_t)(row0 + 8) * D_OUT + col) = v1;
        }
    }
}

// ============================================================================
extern "C" void kernel_launch(void* const* d_in, const int* in_sizes, int n_in,
                              void* d_out, int out_size)
{
    (void)in_sizes; (void)n_in; (void)out_size;
    const float* X     = (const float*)d_in[0];
    const float* W     = (const float*)d_in[1];
    const float* bias  = (const float*)d_in[2];
    const float* Acat  = (const float*)d_in[3];   // (N,R,D) flattens to (64,1280)
    const float* Bw    = (const float*)d_in[4];
    const float* scal  = (const float*)d_in[5];
    const float* masks = (const float*)d_in[6];
    float* out = (float*)d_out;

    lora_g_kernel<<<M_ROWS / 128, 256>>>(X, Acat, scal, masks);
    lora_main_kernel<<<dim3(D_OUT / 128, M_ROWS / 128), 128>>>(X, W, bias, Bw, out);
}

// round 7
// speedup vs baseline: 2.5201x; 1.8468x over previous
#include <cuda_runtime.h>
#include <cstdint>

#define DEVINL __device__ __forceinline__

// ---------------- problem dims ----------------
#define B_SZ   8
#define S_SZ   4096
#define D_IN   1280
#define D_OUT  1280
#define N_L    4
#define R_L    16
#define J_L    64                 /* N_L * R_L */
#define M_ROWS 32768              /* B_SZ * S_SZ */
#define K_TOT  1344               /* D_IN + J_L  */

// ---------------- tiling ----------------
#define KC    16                  /* K per smem stage */
#define SA    136                 /* g-kernel smem stride */
#define SB1   72
#define NT_MAIN (K_TOT / KC)      /* 84 */
#define NT_G    (D_IN / KC)       /* 80 */

// LoRA intermediate: g[m][j] = scaling[j>>4] * mask[j>>4][m & 4095] * (x[m] . Acat[j])
__device__ float g_scratch[(size_t)M_ROWS * J_L];

// ---------------- helpers ----------------
DEVINL uint32_t tf32b(float x) {          // round-to-nearest tf32 (unbiased) in b32
    uint32_t r;
    asm("cvt.rna.tf32.f32 %0, %1;" : "=r"(r) : "f"(x));
    return r;
}

DEVINL void mma_tf32(float c[4], uint32_t a0, uint32_t a1, uint32_t a2, uint32_t a3,
                     uint32_t b0, uint32_t b1) {
    asm volatile(
        "mma.sync.aligned.m16n8k8.row.col.f32.tf32.tf32.f32 "
        "{%0,%1,%2,%3}, {%4,%5,%6,%7}, {%8,%9}, {%0,%1,%2,%3};"
        : "+f"(c[0]), "+f"(c[1]), "+f"(c[2]), "+f"(c[3])
        : "r"(a0), "r"(a1), "r"(a2), "r"(a3), "r"(b0), "r"(b1));
}

DEVINL void ldsm4(uint32_t r[4], uint32_t addr) {
    asm volatile("ldmatrix.sync.aligned.m8n8.x4.shared.b16 {%0,%1,%2,%3}, [%4];"
                 : "=r"(r[0]), "=r"(r[1]), "=r"(r[2]), "=r"(r[3]) : "r"(addr));
}

DEVINL uint32_t smem_u32(const void* p) {
    uint32_t a;
    asm("{ .reg .u64 t; cvta.to.shared.u64 t, %1; cvt.u32.u64 %0, t; }" : "=r"(a) : "l"(p));
    return a;
}

// XOR-swizzled pair-row layout for a 128(rows) x 16(k floats) tile:
//   float index(m,k) = (m>>1)*32 + (((4*(m&1) + (k>>2)) ^ ((m>>1)&7)) << 2) + (k&3)
// Conflict-free for: coalesced STS.128 fill, ldmatrix phases, no padding (8KB/tile).

// ============================================================================
// Kernel 1: g = (scaling * mask) .* (X @ Acat^T)    [32768 x 64, K = 1280]
//   (unchanged from R6 — ~8% of runtime; main kernel is the target)
// ============================================================================
__global__ void __launch_bounds__(256, 2)
lora_g_kernel(const float* __restrict__ X, const float* __restrict__ Acat,
              const float* __restrict__ scalings, const float* __restrict__ masks)
{
    __shared__ uint32_t As[2][KC * SA];
    __shared__ uint32_t Bs[2][KC * SB1];

    const int tid  = threadIdx.x;
    const int mb   = blockIdx.x * 128;
    const int lane = tid & 31;
    const int wid  = tid >> 5;
    const int gid  = lane >> 2, tig = lane & 3;
    const int moff = (wid >> 1) * 32;
    const int noff = (wid & 1) * 32;

    const int rA  = tid & 127;
    const int cgA = (tid >> 7) * 2;
    const int rB  = tid & 63;
    const int cgB = (tid >> 6) & 3;

    float acc[2][4][4];
    #pragma unroll
    for (int mi = 0; mi < 2; mi++)
        #pragma unroll
        for (int ni = 0; ni < 4; ni++)
            #pragma unroll
            for (int q = 0; q < 4; q++) acc[mi][ni][q] = 0.f;

    float4 ra0, ra1, rb;
    auto ldg = [&](int t) {
        int kb = t * KC;
        const float* pa = X + (size_t)(mb + rA) * D_IN + kb + cgA * 4;
        ra0 = ((const float4*)pa)[0];
        ra1 = ((const float4*)pa)[1];
        rb  = *(const float4*)(Acat + (size_t)rB * D_IN + kb + cgB * 4);
    };
    auto sts = [&](int buf) {
        uint32_t* a = As[buf] + rA;
        a[(cgA * 4 + 0) * SA] = tf32b(ra0.x);
        a[(cgA * 4 + 1) * SA] = tf32b(ra0.y);
        a[(cgA * 4 + 2) * SA] = tf32b(ra0.z);
        a[(cgA * 4 + 3) * SA] = tf32b(ra0.w);
        a[(cgA * 4 + 4) * SA] = tf32b(ra1.x);
        a[(cgA * 4 + 5) * SA] = tf32b(ra1.y);
        a[(cgA * 4 + 6) * SA] = tf32b(ra1.z);
        a[(cgA * 4 + 7) * SA] = tf32b(ra1.w);
        uint32_t* b = Bs[buf] + rB;
        b[(cgB * 4 + 0) * SB1] = tf32b(rb.x);
        b[(cgB * 4 + 1) * SB1] = tf32b(rb.y);
        b[(cgB * 4 + 2) * SB1] = tf32b(rb.z);
        b[(cgB * 4 + 3) * SB1] = tf32b(rb.w);
    };
    auto domma = [&](int buf) {
        #pragma unroll
        for (int ks = 0; ks < 2; ks++) {
            const int k0 = ks * 8;
            uint32_t af[2][4], bf[4][2];
            #pragma unroll
            for (int mi = 0; mi < 2; mi++) {
                const uint32_t* p = As[buf] + moff + mi * 16 + gid;
                af[mi][0] = p[(k0 + tig) * SA];
                af[mi][1] = p[(k0 + tig) * SA + 8];
                af[mi][2] = p[(k0 + tig + 4) * SA];
                af[mi][3] = p[(k0 + tig + 4) * SA + 8];
            }
            #pragma unroll
            for (int ni = 0; ni < 4; ni++) {
                const uint32_t* p = Bs[buf] + noff + ni * 8 + gid;
                bf[ni][0] = p[(k0 + tig) * SB1];
                bf[ni][1] = p[(k0 + tig + 4) * SB1];
            }
            #pragma unroll
            for (int mi = 0; mi < 2; mi++)
                #pragma unroll
                for (int ni = 0; ni < 4; ni++)
                    mma_tf32(acc[mi][ni], af[mi][0], af[mi][1], af[mi][2], af[mi][3],
                             bf[ni][0], bf[ni][1]);
        }
    };

    ldg(0); sts(0); ldg(1);
    __syncthreads();
    for (int t = 0; t < NT_G; t++) {
        if (t + 1 < NT_G) {
            sts((t + 1) & 1);
            if (t + 2 < NT_G) ldg(t + 2);
        }
        domma(t & 1);
        __syncthreads();
    }

    float coef[2][2][2];
    #pragma unroll
    for (int mi = 0; mi < 2; mi++)
        #pragma unroll
        for (int h = 0; h < 2; h++) {
            int m = mb + moff + mi * 16 + gid + h * 8;
            int s = m & (S_SZ - 1);
            #pragma unroll
            for (int sl = 0; sl < 2; sl++) {
                int subj = (noff >> 4) + sl;
                coef[mi][h][sl] = scalings[subj] * masks[subj * S_SZ + s];
            }
        }
    #pragma unroll
    for (int mi = 0; mi < 2; mi++)
        #pragma unroll
        for (int ni = 0; ni < 4; ni++) {
            int col = noff + ni * 8 + 2 * tig;
            int sl  = (ni * 8 + 2 * tig) >> 4;
            int row0 = mb + moff + mi * 16 + gid;
            float2 v0 = { acc[mi][ni][0] * coef[mi][0][sl], acc[mi][ni][1] * coef[mi][0][sl] };
            float2 v1 = { acc[mi][ni][2] * coef[mi][1][sl], acc[mi][ni][3] * coef[mi][1][sl] };
            *(float2*)(g_scratch + (size_t)row0 * J_L + col)       = v0;
            *(float2*)(g_scratch + (size_t)(row0 + 8) * J_L + col) = v1;
        }
}

// ============================================================================
// Kernel 2: out = X @ W^T + bias + g @ Bcat^T   [one GEMM, K = 1344]
//   128 threads, 128x128 CTA tile, 4 warps (2m x 2n), warp tile 64x64.
//   Coalesced fill (4 lanes / 64B row-chunk), XOR-swizzled smem, ldmatrix frags.
// ============================================================================
__global__ void __launch_bounds__(128, 2)
lora_main_kernel(const float* __restrict__ X, const float* __restrict__ W,
                 const float* __restrict__ bias, const float* __restrict__ Bw,
                 float* __restrict__ out)
{
    __shared__ uint32_t As[2][2048];      // 8KB per buffer, XOR-swizzled
    __shared__ uint32_t Bs[2][2048];

    const int tid  = threadIdx.x;
    const int nb   = blockIdx.x * 128;    // x fastest: CTAs share the X tile via L2
    const int mb   = blockIdx.y * 128;
    const int lane = tid & 31;
    const int wid  = tid >> 5;
    const int gid  = lane >> 2, tig = lane & 3;
    const int moff = (wid & 1) * 64;
    const int noff = (wid >> 1) * 64;

    // ---- fill mapping: 4 passes; pass i handles (m = (tid+128i)>>2, c = (tid+128i)&3)
    int fm[4], fc[4];
    uint32_t fOffA[4];                    // swizzled float index (16B-aligned)
    #pragma unroll
    for (int i = 0; i < 4; i++) {
        int idx = tid + i * 128;
        int m = idx >> 2, c = idx & 3;
        fm[i] = m; fc[i] = c;
        int p = m >> 1, q = m & 1;
        fOffA[i] = (uint32_t)(p * 32 + (((4 * q + c) ^ (p & 7)) << 2));
    }

    // ---- ldmatrix per-lane base addresses (buffer 0), ks in {0,1}
    const uint32_t aBase = smem_u32(&As[0][0]);
    const uint32_t bBase = smem_u32(&Bs[0][0]);
    uint32_t aAddr[2], bAddr[2];
    {
        int sub  = lane & 15;
        int half = lane >> 4;
        int m = moff + sub, p = m >> 1, q = m & 1;
        #pragma unroll
        for (int ks = 0; ks < 2; ks++) {
            int c = 2 * ks + half;
            aAddr[ks] = aBase + (uint32_t)(p * 32 + (((4 * q + c) ^ (p & 7)) << 2)) * 4u;
        }
        int nsub  = (lane & 7) + ((lane >> 4) << 3);
        int bhalf = (lane >> 3) & 1;
        int n = noff + nsub; p = n >> 1; q = n & 1;
        #pragma unroll
        for (int ks = 0; ks < 2; ks++) {
            int c = 2 * ks + bhalf;
            bAddr[ks] = bBase + (uint32_t)(p * 32 + (((4 * q + c) ^ (p & 7)) << 2)) * 4u;
        }
    }

    float acc[4][8][4];
    #pragma unroll
    for (int mi = 0; mi < 4; mi++)
        #pragma unroll
        for (int ni = 0; ni < 8; ni++)
            #pragma unroll
            for (int q = 0; q < 4; q++) acc[mi][ni][q] = 0.f;

    float4 ra[4], rb[4];
    auto ldg = [&](int t) {
        int kb = t * KC;
        if (kb < D_IN) {
            #pragma unroll
            for (int i = 0; i < 4; i++) {
                ra[i] = *(const float4*)(X + (size_t)(mb + fm[i]) * D_IN + kb + fc[i] * 4);
                rb[i] = *(const float4*)(W + (size_t)(nb + fm[i]) * D_IN + kb + fc[i] * 4);
            }
        } else {
            int j0 = kb - D_IN;               // 0,16,32,48
            #pragma unroll
            for (int i = 0; i < 4; i++) {
                ra[i] = *(const float4*)(g_scratch + (size_t)(mb + fm[i]) * J_L + j0 + fc[i] * 4);
                // Bcat[o][j] = Bw[j>>4][o][j&15]
                rb[i] = *(const float4*)(Bw + (size_t)(j0 >> 4) * (D_OUT * R_L)
                                            + (size_t)(nb + fm[i]) * R_L + fc[i] * 4);
            }
        }
    };
    auto sts = [&](int buf) {
        #pragma unroll
        for (int i = 0; i < 4; i++) {
            uint4 va = { tf32b(ra[i].x), tf32b(ra[i].y), tf32b(ra[i].z), tf32b(ra[i].w) };
            uint4 vb = { tf32b(rb[i].x), tf32b(rb[i].y), tf32b(rb[i].z), tf32b(rb[i].w) };
            *(uint4*)&As[buf][fOffA[i]] = va;
            *(uint4*)&Bs[buf][fOffA[i]] = vb;
        }
    };
    auto domma = [&](int buf) {
        const uint32_t bo = (uint32_t)buf * 8192u;
        #pragma unroll
        for (int ks = 0; ks < 2; ks++) {
            uint32_t a[4][4], b[4][4];
            #pragma unroll
            for (int mi = 0; mi < 4; mi++)
                ldsm4(a[mi], aAddr[ks] + bo + (uint32_t)mi * 1024u);
            #pragma unroll
            for (int nj = 0; nj < 4; nj++)
                ldsm4(b[nj], bAddr[ks] + bo + (uint32_t)nj * 1024u);
            #pragma unroll
            for (int mi = 0; mi < 4; mi++)
                #pragma unroll
                for (int ni = 0; ni < 8; ni++)
                    mma_tf32(acc[mi][ni], a[mi][0], a[mi][1], a[mi][2], a[mi][3],
                             b[ni >> 1][(ni & 1) * 2], b[ni >> 1][(ni & 1) * 2 + 1]);
        }
    };

    ldg(0); sts(0); ldg(1);
    __syncthreads();
    for (int t = 0; t < NT_MAIN; t++) {
        if (t + 1 < NT_MAIN) {
            sts((t + 1) & 1);
            if (t + 2 < NT_MAIN) ldg(t + 2);
        }
        domma(t & 1);
        __syncthreads();
    }

    // epilogue: + bias, float2 stores
    #pragma unroll
    for (int ni = 0; ni < 8; ni++) {
        int col = nb + noff + ni * 8 + 2 * tig;
        float2 bb = *(const float2*)(bias + col);
        #pragma unroll
        for (int mi = 0; mi < 4; mi++) {
            int row0 = mb + moff + mi * 16 + gid;
            float2 v0 = { acc[mi][ni][0] + bb.x, acc[mi][ni][1] + bb.y };
            float2 v1 = { acc[mi][ni][2] + bb.x, acc[mi][ni][3] + bb.y };
            *(float2*)(out + (size_t)row0 * D_OUT + col)       = v0;
            *(float2*)(out + (size_t)(row0 + 8) * D_OUT + col) = v1;
        }
    }
}

// ============================================================================
extern "C" void kernel_launch(void* const* d_in, const int* in_sizes, int n_in,
                              void* d_out, int out_size)
{
    (void)in_sizes; (void)n_in; (void)out_size;
    const float* X     = (const float*)d_in[0];
    const float* W     = (const float*)d_in[1];
    const float* bias  = (const float*)d_in[2];
    const float* Acat  = (const float*)d_in[3];   // (N,R,D) flattens to (64,1280)
    const float* Bw    = (const float*)d_in[4];
    const float* scal  = (const float*)d_in[5];
    const float* masks = (const float*)d_in[6];
    float* out = (float*)d_out;

    lora_g_kernel<<<M_ROWS / 128, 256>>>(X, Acat, scal, masks);
    lora_main_kernel<<<dim3(D_OUT / 128, M_ROWS / 128), 128>>>(X, W, bias, Bw, out);
}

// round 8
// speedup vs baseline: 2.9099x; 1.1547x over previous
#include <cuda_runtime.h>
#include <cstdint>

#define DEVINL __device__ __forceinline__

// ---------------- problem dims ----------------
#define B_SZ   8
#define S_SZ   4096
#define D_IN   1280
#define D_OUT  1280
#define N_L    4
#define R_L    16
#define J_L    64                 /* N_L * R_L */
#define M_ROWS 32768              /* B_SZ * S_SZ */
#define K_TOT  1344               /* D_IN + J_L  */

// ---------------- tiling ----------------
#define KC      16                /* K per stage */
#define NT_ALL  (K_TOT / KC)      /* 84 stages (80 X + 4 LoRA) */
#define NT_X    (D_IN / KC)       /* 80 */
#define NT_G    (D_IN / KC)       /* 80 (g kernel mainloop) */
#define STAGES  4
#define SA      136               /* g-kernel smem stride */
#define SB1     72

// Pre-swizzled, tf32-pre-rounded operand tensors.
//   Xt[mtile][ktile][2048 floats]  (mtile = m>>7, ktile = k>>4)
//   Wt[ntile][ktile][2048 floats]
// In-tile layout (m = row&127, kk = k&15):
//   fidx(m,kk) = (m>>1)*32 + (((4*(m&1) + (kk>>2)) ^ ((m>>1)&7)) << 2) + (kk&3)
__device__ float Xt[(size_t)(M_ROWS / 128) * NT_ALL * 2048];
__device__ float Wt[(size_t)(D_OUT / 128) * NT_ALL * 2048];

// ---------------- helpers ----------------
DEVINL uint32_t tf32b(float x) {          // round-to-nearest tf32 (unbiased) in b32
    uint32_t r;
    asm("cvt.rna.tf32.f32 %0, %1;" : "=r"(r) : "f"(x));
    return r;
}
DEVINL float tf32f(float x) { uint32_t r = tf32b(x); return __uint_as_float(r); }

DEVINL void mma_tf32(float c[4], uint32_t a0, uint32_t a1, uint32_t a2, uint32_t a3,
                     uint32_t b0, uint32_t b1) {
    asm volatile(
        "mma.sync.aligned.m16n8k8.row.col.f32.tf32.tf32.f32 "
        "{%0,%1,%2,%3}, {%4,%5,%6,%7}, {%8,%9}, {%0,%1,%2,%3};"
        : "+f"(c[0]), "+f"(c[1]), "+f"(c[2]), "+f"(c[3])
        : "r"(a0), "r"(a1), "r"(a2), "r"(a3), "r"(b0), "r"(b1));
}
DEVINL void ldsm4(uint32_t r[4], uint32_t addr) {
    asm volatile("ldmatrix.sync.aligned.m8n8.x4.shared.b16 {%0,%1,%2,%3}, [%4];"
                 : "=r"(r[0]), "=r"(r[1]), "=r"(r[2]), "=r"(r[3]) : "r"(addr));
}
DEVINL uint32_t smem_u32(const void* p) {
    uint32_t a;
    asm("{ .reg .u64 t; cvta.to.shared.u64 t, %1; cvt.u32.u64 %0, t; }" : "=r"(a) : "l"(p));
    return a;
}
DEVINL void cp16(uint32_t smem, const void* gptr) {
    asm volatile("cp.async.cg.shared.global [%0], [%1], 16;" :: "r"(smem), "l"(gptr) : "memory");
}
#define CP_COMMIT() asm volatile("cp.async.commit_group;" ::: "memory")
#define CP_WAIT2()  asm volatile("cp.async.wait_group 2;" ::: "memory")

DEVINL uint32_t fidx_sw(int m, int kk) {
    int p = m >> 1, q = m & 1;
    return (uint32_t)(p * 32 + (((4 * q + (kk >> 2)) ^ (p & 7)) << 2) + (kk & 3));
}

// ============================================================================
// Kernel 0a: Xt[mt][kt<80] = swizzled tf32(X)       grid (256, 80), 128 thr
//   Per-warp: reads 4 lanes/64B row-chunk (coalesced); writes are 512B-
//   contiguous per warp under the swizzle (groups permute within pair-rows).
// ============================================================================
__global__ void __launch_bounds__(128)
convert_x_kernel(const float* __restrict__ X)
{
    const int tid = threadIdx.x;
    const int mt = blockIdx.x, kt = blockIdx.y;
    float* dst = Xt + ((size_t)mt * NT_ALL + kt) * 2048;
    #pragma unroll
    for (int i = 0; i < 4; i++) {
        int idx = tid + i * 128;
        int m = idx >> 2, c = idx & 3;
        float4 v = *(const float4*)(X + (size_t)(mt * 128 + m) * D_IN + kt * KC + c * 4);
        float4 o = { tf32f(v.x), tf32f(v.y), tf32f(v.z), tf32f(v.w) };
        *(float4*)(dst + fidx_sw(m, c * 4)) = o;
    }
}

// ============================================================================
// Kernel 0b: Wt[nt][kt] from W (kt<80) / Bcat gather (kt>=80)   grid (10, 84)
//   Bcat[o][j] = Bw[j>>4][o][j&15]
// ============================================================================
__global__ void __launch_bounds__(128)
convert_w_kernel(const float* __restrict__ W, const float* __restrict__ Bw)
{
    const int tid = threadIdx.x;
    const int nt = blockIdx.x, kt = blockIdx.y;
    float* dst = Wt + ((size_t)nt * NT_ALL + kt) * 2048;
    #pragma unroll
    for (int i = 0; i < 4; i++) {
        int idx = tid + i * 128;
        int m = idx >> 2, c = idx & 3;
        float4 v;
        if (kt < NT_X) {
            v = *(const float4*)(W + (size_t)(nt * 128 + m) * D_IN + kt * KC + c * 4);
        } else {
            v = *(const float4*)(Bw + (size_t)(kt - NT_X) * (D_OUT * R_L)
                                    + (size_t)(nt * 128 + m) * R_L + c * 4);
        }
        float4 o = { tf32f(v.x), tf32f(v.y), tf32f(v.z), tf32f(v.w) };
        *(float4*)(dst + fidx_sw(m, c * 4)) = o;
    }
}

// ============================================================================
// Kernel 1: LoRA activations -> Xt ktiles 80..83
//   g[m][j] = scaling[j>>4]*mask[j>>4][m&4095] * (x[m].Acat[j]),  tf32-rounded,
//   stored in the swizzled tile layout.  Mainloop as in R7.
// ============================================================================
__global__ void __launch_bounds__(256, 2)
lora_g_kernel(const float* __restrict__ X, const float* __restrict__ Acat,
              const float* __restrict__ scalings, const float* __restrict__ masks)
{
    __shared__ uint32_t As[2][KC * SA];
    __shared__ uint32_t Bs[2][KC * SB1];

    const int tid  = threadIdx.x;
    const int mb   = blockIdx.x * 128;
    const int lane = tid & 31;
    const int wid  = tid >> 5;
    const int gid  = lane >> 2, tig = lane & 3;
    const int moff = (wid >> 1) * 32;
    const int noff = (wid & 1) * 32;

    const int rA  = tid & 127;
    const int cgA = (tid >> 7) * 2;
    const int rB  = tid & 63;
    const int cgB = (tid >> 6) & 3;

    float acc[2][4][4];
    #pragma unroll
    for (int mi = 0; mi < 2; mi++)
        #pragma unroll
        for (int ni = 0; ni < 4; ni++)
            #pragma unroll
            for (int q = 0; q < 4; q++) acc[mi][ni][q] = 0.f;

    float4 ra0, ra1, rb;
    auto ldg = [&](int t) {
        int kb = t * KC;
        const float* pa = X + (size_t)(mb + rA) * D_IN + kb + cgA * 4;
        ra0 = ((const float4*)pa)[0];
        ra1 = ((const float4*)pa)[1];
        rb  = *(const float4*)(Acat + (size_t)rB * D_IN + kb + cgB * 4);
    };
    auto sts = [&](int buf) {
        uint32_t* a = As[buf] + rA;
        a[(cgA * 4 + 0) * SA] = tf32b(ra0.x);
        a[(cgA * 4 + 1) * SA] = tf32b(ra0.y);
        a[(cgA * 4 + 2) * SA] = tf32b(ra0.z);
        a[(cgA * 4 + 3) * SA] = tf32b(ra0.w);
        a[(cgA * 4 + 4) * SA] = tf32b(ra1.x);
        a[(cgA * 4 + 5) * SA] = tf32b(ra1.y);
        a[(cgA * 4 + 6) * SA] = tf32b(ra1.z);
        a[(cgA * 4 + 7) * SA] = tf32b(ra1.w);
        uint32_t* b = Bs[buf] + rB;
        b[(cgB * 4 + 0) * SB1] = tf32b(rb.x);
        b[(cgB * 4 + 1) * SB1] = tf32b(rb.y);
        b[(cgB * 4 + 2) * SB1] = tf32b(rb.z);
        b[(cgB * 4 + 3) * SB1] = tf32b(rb.w);
    };
    auto domma = [&](int buf) {
        #pragma unroll
        for (int ks = 0; ks < 2; ks++) {
            const int k0 = ks * 8;
            uint32_t af[2][4], bf[4][2];
            #pragma unroll
            for (int mi = 0; mi < 2; mi++) {
                const uint32_t* p = As[buf] + moff + mi * 16 + gid;
                af[mi][0] = p[(k0 + tig) * SA];
                af[mi][1] = p[(k0 + tig) * SA + 8];
                af[mi][2] = p[(k0 + tig + 4) * SA];
                af[mi][3] = p[(k0 + tig + 4) * SA + 8];
            }
            #pragma unroll
            for (int ni = 0; ni < 4; ni++) {
                const uint32_t* p = Bs[buf] + noff + ni * 8 + gid;
                bf[ni][0] = p[(k0 + tig) * SB1];
                bf[ni][1] = p[(k0 + tig + 4) * SB1];
            }
            #pragma unroll
            for (int mi = 0; mi < 2; mi++)
                #pragma unroll
                for (int ni = 0; ni < 4; ni++)
                    mma_tf32(acc[mi][ni], af[mi][0], af[mi][1], af[mi][2], af[mi][3],
                             bf[ni][0], bf[ni][1]);
        }
    };

    ldg(0); sts(0); ldg(1);
    __syncthreads();
    for (int t = 0; t < NT_G; t++) {
        if (t + 1 < NT_G) {
            sts((t + 1) & 1);
            if (t + 2 < NT_G) ldg(t + 2);
        }
        domma(t & 1);
        __syncthreads();
    }

    float coef[2][2][2];
    #pragma unroll
    for (int mi = 0; mi < 2; mi++)
        #pragma unroll
        for (int h = 0; h < 2; h++) {
            int m = mb + moff + mi * 16 + gid + h * 8;
            int s = m & (S_SZ - 1);
            #pragma unroll
            for (int sl = 0; sl < 2; sl++) {
                int subj = (noff >> 4) + sl;
                coef[mi][h][sl] = scalings[subj] * masks[subj * S_SZ + s];
            }
        }
    // store into Xt ktiles 80..83, swizzled + tf32-rounded
    float* xblk = Xt + (size_t)(mb >> 7) * NT_ALL * 2048;
    #pragma unroll
    for (int mi = 0; mi < 2; mi++)
        #pragma unroll
        for (int ni = 0; ni < 4; ni++) {
            int col = noff + ni * 8 + 2 * tig;    // 0..63
            int sl  = (ni * 8 + 2 * tig) >> 4;
            int kt  = NT_X + (col >> 4);
            int kk  = col & 15;
            #pragma unroll
            for (int h = 0; h < 2; h++) {
                int r = moff + mi * 16 + gid + h * 8;
                float2 v = { tf32f(acc[mi][ni][2 * h + 0] * coef[mi][h][sl]),
                             tf32f(acc[mi][ni][2 * h + 1] * coef[mi][h][sl]) };
                *(float2*)(xblk + (size_t)kt * 2048 + fidx_sw(r, kk)) = v;
            }
        }
}

// ============================================================================
// Kernel 2: out = [X|g] @ [W|Bcat]^T + bias   (K = 1344, all from Xt/Wt)
//   128 threads, 128x128 tile, 4 warps (2m x 2n), warp tile 64x64.
//   4-stage cp.async.cg pipeline, identity-offset fills, ldmatrix fragments.
// ============================================================================
__global__ void __launch_bounds__(128, 2)
lora_main_kernel(const float* __restrict__ bias, float* __restrict__ out)
{
    __shared__ float As[STAGES][2048];
    __shared__ float Bs[STAGES][2048];

    const int tid  = threadIdx.x;
    const int nt   = blockIdx.x;          // x fastest: 10 CTAs share the Xt blocks via L2
    const int mt   = blockIdx.y;
    const int lane = tid & 31;
    const int wid  = tid >> 5;
    const int gid  = lane >> 2, tig = lane & 3;
    const int moff = (wid & 1) * 64;
    const int noff = (wid >> 1) * 64;

    const uint32_t aSm = smem_u32(&As[0][0]);
    const uint32_t bSm = smem_u32(&Bs[0][0]);

    // ldmatrix per-lane addresses for buffer 0, ks in {0,1}
    uint32_t aAddr[2], bAddr[2];
    {
        int sub  = lane & 15;
        int half = lane >> 4;
        #pragma unroll
        for (int ks = 0; ks < 2; ks++)
            aAddr[ks] = aSm + fidx_sw(moff + sub, (2 * ks + half) * 4) * 4u;
        int nsub  = (lane & 7) + ((lane >> 4) << 3);
        int bhalf = (lane >> 3) & 1;
        #pragma unroll
        for (int ks = 0; ks < 2; ks++)
            bAddr[ks] = bSm + fidx_sw(noff + nsub, (2 * ks + bhalf) * 4) * 4u;
    }

    const float* srcA = Xt + (size_t)mt * NT_ALL * 2048 + tid * 4;
    const float* srcB = Wt + (size_t)nt * NT_ALL * 2048 + tid * 4;

    float acc[4][8][4];
    #pragma unroll
    for (int mi = 0; mi < 4; mi++)
        #pragma unroll
        for (int ni = 0; ni < 8; ni++)
            #pragma unroll
            for (int q = 0; q < 4; q++) acc[mi][ni][q] = 0.f;

    auto fill = [&](int t, int buf) {
        uint32_t da = aSm + (uint32_t)buf * 8192u + (uint32_t)tid * 16u;
        uint32_t db = bSm + (uint32_t)buf * 8192u + (uint32_t)tid * 16u;
        const float* sa = srcA + (size_t)t * 2048;
        const float* sb = srcB + (size_t)t * 2048;
        #pragma unroll
        for (int i = 0; i < 4; i++) {
            cp16(da + i * 2048u, sa + i * 512);
            cp16(db + i * 2048u, sb + i * 512);
        }
    };
    auto domma = [&](int buf) {
        const uint32_t bo = (uint32_t)buf * 8192u;
        #pragma unroll
        for (int ks = 0; ks < 2; ks++) {
            uint32_t a[4][4], b[4][4];
            #pragma unroll
            for (int mi = 0; mi < 4; mi++)
                ldsm4(a[mi], aAddr[ks] + bo + (uint32_t)mi * 1024u);
            #pragma unroll
            for (int nj = 0; nj < 4; nj++)
                ldsm4(b[nj], bAddr[ks] + bo + (uint32_t)nj * 1024u);
            #pragma unroll
            for (int mi = 0; mi < 4; mi++)
                #pragma unroll
                for (int ni = 0; ni < 8; ni++)
                    mma_tf32(acc[mi][ni], a[mi][0], a[mi][1], a[mi][2], a[mi][3],
                             b[ni >> 1][(ni & 1) * 2], b[ni >> 1][(ni & 1) * 2 + 1]);
        }
    };

    #pragma unroll
    for (int t = 0; t < STAGES - 1; t++) { fill(t, t); CP_COMMIT(); }

    for (int t = 0; t < NT_ALL; t++) {
        CP_WAIT2();
        __syncthreads();
        if (t + STAGES - 1 < NT_ALL) fill(t + STAGES - 1, (t + STAGES - 1) & (STAGES - 1));
        CP_COMMIT();
        domma(t & (STAGES - 1));
    }

    // epilogue: + bias, float2 stores
    const int nb = nt * 128, mb = mt * 128;
    #pragma unroll
    for (int ni = 0; ni < 8; ni++) {
        int col = nb + noff + ni * 8 + 2 * tig;
        float2 bb = *(const float2*)(bias + col);
        #pragma unroll
        for (int mi = 0; mi < 4; mi++) {
            int row0 = mb + moff + mi * 16 + gid;
            float2 v0 = { acc[mi][ni][0] + bb.x, acc[mi][ni][1] + bb.y };
            float2 v1 = { acc[mi][ni][2] + bb.x, acc[mi][ni][3] + bb.y };
            *(float2*)(out + (size_t)row0 * D_OUT + col)       = v0;
            *(float2*)(out + (size_t)(row0 + 8) * D_OUT + col) = v1;
        }
    }
}

// ============================================================================
extern "C" void kernel_launch(void* const* d_in, const int* in_sizes, int n_in,
                              void* d_out, int out_size)
{
    (void)in_sizes; (void)n_in; (void)out_size;
    const float* X     = (const float*)d_in[0];
    const float* W     = (const float*)d_in[1];
    const float* bias  = (const float*)d_in[2];
    const float* Acat  = (const float*)d_in[3];   // (N,R,D) flattens to (64,1280)
    const float* Bw    = (const float*)d_in[4];
    const float* scal  = (const float*)d_in[5];
    const float* masks = (const float*)d_in[6];
    float* out = (float*)d_out;

    convert_x_kernel<<<dim3(M_ROWS / 128, NT_X), 128>>>(X);
    convert_w_kernel<<<dim3(D_OUT / 128, NT_ALL), 128>>>(W, Bw);
    lora_g_kernel<<<M_ROWS / 128, 256>>>(X, Acat, scal, masks);
    lora_main_kernel<<<dim3(D_OUT / 128, M_ROWS / 128), 128>>>(bias, out);
}